// round 6
// baseline (speedup 1.0000x reference)
#include <cuda_runtime.h>
#include <cuda_fp16.h>
#include <math.h>
#include <stdint.h>

#define TT 512
#define NN 1024
#define DD 256
#define M_ROWS (TT * NN)

__device__ float g_epart[2 * M_ROWS];          // N-split partial scores
__device__ __align__(16) __half g_Whi[DD * DD];

// ---------------------------------------------------------------------------
// SMEM (per CTA, dynamic, 90112 B -> 2 CTAs/SM):
//   B resident: 128 rows * 528 B (512 data + 16 pad; 528%128=16 -> LDSM clean)
//   A double-buffer: 2 * 128 rows * 80 B
// ---------------------------------------------------------------------------
#define SB_OFF     0
#define SB_ROW     528
#define SA(buf)    (67584 + (buf) * 10240)
#define SBIAS      88064
#define SSW        88576
#define SRED       89088
#define SMTOT      90112

// ---------------------------------------------------------------------------
// PTX helpers (baseline ISA only -- toolchain targets sm_103, no tcgen05)
// ---------------------------------------------------------------------------
__device__ __forceinline__ uint32_t smem_u32(const void* p) {
    uint32_t a;
    asm("{ .reg .u64 t; cvta.to.shared.u64 t, %1; cvt.u32.u64 %0, t; }"
        : "=r"(a) : "l"(p));
    return a;
}
__device__ __forceinline__ void cp_async16(uint32_t dst, const void* src) {
    asm volatile("cp.async.cg.shared.global [%0], [%1], 16;"
                 :: "r"(dst), "l"(src) : "memory");
}
#define CP_COMMIT() asm volatile("cp.async.commit_group;" ::: "memory")
#define CP_WAIT(n)  asm volatile("cp.async.wait_group %0;" :: "n"(n) : "memory")

__device__ __forceinline__ void ldsm4(uint32_t* r, uint32_t addr) {
    asm volatile("ldmatrix.sync.aligned.m8n8.x4.shared.b16 {%0,%1,%2,%3}, [%4];"
                 : "=r"(r[0]), "=r"(r[1]), "=r"(r[2]), "=r"(r[3]) : "r"(addr));
}
__device__ __forceinline__ void mma16816(float* c, const uint32_t* a,
                                         uint32_t b0, uint32_t b1) {
    asm volatile(
        "mma.sync.aligned.m16n8k16.row.col.f32.f16.f16.f32 "
        "{%0,%1,%2,%3}, {%4,%5,%6,%7}, {%8,%9}, {%0,%1,%2,%3};"
        : "+f"(c[0]), "+f"(c[1]), "+f"(c[2]), "+f"(c[3])
        : "r"(a[0]), "r"(a[1]), "r"(a[2]), "r"(a[3]), "r"(b0), "r"(b1));
}

// fp32 x8 -> fp16 x8
__device__ __forceinline__ uint4 cvt8hi(const float4& u, const float4& v) {
    __half2 h0 = __floats2half2_rn(u.x, u.y);
    __half2 h1 = __floats2half2_rn(u.z, u.w);
    __half2 h2 = __floats2half2_rn(v.x, v.y);
    __half2 h3 = __floats2half2_rn(v.z, v.w);
    uint4 hi;
    hi.x = *(uint32_t*)&h0; hi.y = *(uint32_t*)&h1;
    hi.z = *(uint32_t*)&h2; hi.w = *(uint32_t*)&h3;
    return hi;
}

// tanh via MUFU (EX2 + RCP), rel err ~1e-6
__device__ __forceinline__ float tanh_mufu(float z) {
    float u = __expf(2.0f * z);
    return 1.0f - __fdividef(2.0f, u + 1.0f);
}

// ---------------------------------------------------------------------------
__global__ void w_prep(const float* __restrict__ W) {
    int i = blockIdx.x * blockDim.x + threadIdx.x;
    const float4* p = reinterpret_cast<const float4*>(W) + i * 2;
    reinterpret_cast<uint4*>(g_Whi)[i] = cvt8hi(p[0], p[1]);
}

// ---------------------------------------------------------------------------
// Kernel A: fp16 HMMA GEMM, BM=128 x BN=128, 256 threads, 2 CTAs/SM.
// grid = 8192: row0 = (blk>>1)*128, col-half = blk&1.
// ---------------------------------------------------------------------------
__global__ __launch_bounds__(256, 2)
void gemm_score_hmma(const float* __restrict__ H,
                     const float* __restrict__ bias,
                     const float* __restrict__ swt)
{
    extern __shared__ char smem[];
    const uint32_t sb = smem_u32(smem);
    const int tid  = threadIdx.x;
    const int lane = tid & 31;
    const int warp = tid >> 5;          // 0..7
    const int wr   = warp >> 1;         // 0..3: rows 32*wr
    const int wc   = warp & 1;          // 0..1: cols 64*wc
    const int half = blockIdx.x & 1;    // N-half
    const int row0 = (blockIdx.x >> 1) * 128;
    const int col0 = half * 128;

    // ---- B resident load: 128 rows x 512 B = 4096 x 16B chunks ----
    #pragma unroll
    for (int p = 0; p < 16; p++) {
        int idx = tid + p * 256;
        int r   = idx >> 5;             // 0..127
        int ch  = idx & 31;             // 0..31
        cp_async16(sb + SB_OFF + r * SB_ROW + ch * 16,
                   g_Whi + (size_t)(col0 + r) * DD + ch * 8);
    }
    CP_COMMIT();

    if (tid < 128) {
        ((float*)(smem + SBIAS))[tid] = bias[col0 + tid];
        ((float*)(smem + SSW))[tid]   = swt[col0 + tid];
    }

    // A loaders: 512 slots (128 rows x 4 ksegs), 2 per thread
    const int ar0_ = (tid + 0)   >> 2, ak0 = (tid + 0)   & 3;
    const int ar1_ = (tid + 256) >> 2, ak1 = (tid + 256) & 3;
    const float* ap0 = H + (size_t)(row0 + ar0_) * DD + ak0 * 8;
    const float* ap1 = H + (size_t)(row0 + ar1_) * DD + ak1 * 8;
    const uint32_t sts0 = (uint32_t)(ar0_ * 80 + ak0 * 16);
    const uint32_t sts1 = (uint32_t)(ar1_ * 80 + ak1 * 16);

    float acc[2][8][4];
    #pragma unroll
    for (int m = 0; m < 2; m++)
        #pragma unroll
        for (int n = 0; n < 8; n++)
            #pragma unroll
            for (int e = 0; e < 4; e++) acc[m][n][e] = 0.0f;

    // ldmatrix lane addressing
    const int lrow = lane & 15;
    const int lkh  = lane >> 4;
    const uint32_t aAddr = sb + (uint32_t)((wr * 32 + lrow) * 80 + lkh * 16);
    const uint32_t bAddr = sb + SB_OFF +
                           (uint32_t)((wc * 64 + lrow) * SB_ROW + lkh * 16);

    // ---- prologue: A chunk 0 ----
    float4 r0a, r0b, r1a, r1b;
    r0a = *reinterpret_cast<const float4*>(ap0);
    r0b = *reinterpret_cast<const float4*>(ap0 + 4);
    r1a = *reinterpret_cast<const float4*>(ap1);
    r1b = *reinterpret_cast<const float4*>(ap1 + 4);
    *reinterpret_cast<uint4*>(smem + SA(0) + sts0) = cvt8hi(r0a, r0b);
    *reinterpret_cast<uint4*>(smem + SA(0) + sts1) = cvt8hi(r1a, r1b);
    r0a = *reinterpret_cast<const float4*>(ap0 + 32);
    r0b = *reinterpret_cast<const float4*>(ap0 + 36);
    r1a = *reinterpret_cast<const float4*>(ap1 + 32);
    r1b = *reinterpret_cast<const float4*>(ap1 + 36);
    CP_WAIT(0);
    __syncthreads();

    #pragma unroll
    for (int c = 0; c < 8; c++) {
        const int buf = c & 1;
        if (c < 7) {
            *reinterpret_cast<uint4*>(smem + SA(buf ^ 1) + sts0) =
                cvt8hi(r0a, r0b);
            *reinterpret_cast<uint4*>(smem + SA(buf ^ 1) + sts1) =
                cvt8hi(r1a, r1b);
        }
        if (c < 6) {
            r0a = *reinterpret_cast<const float4*>(ap0 + (c + 2) * 32);
            r0b = *reinterpret_cast<const float4*>(ap0 + (c + 2) * 32 + 4);
            r1a = *reinterpret_cast<const float4*>(ap1 + (c + 2) * 32);
            r1b = *reinterpret_cast<const float4*>(ap1 + (c + 2) * 32 + 4);
        }

        // ---- MMA chunk c (B resident: k-offset = c*64 bytes) ----
        const uint32_t aA = aAddr + SA(buf);
        const uint32_t bB = bAddr + (uint32_t)(c * 64);
        #pragma unroll
        for (int ks = 0; ks < 2; ks++) {
            uint32_t ah[2][4];
            ldsm4(ah[0], aA + ks * 32);
            ldsm4(ah[1], aA + 16 * 80 + ks * 32);
            #pragma unroll
            for (int ntp = 0; ntp < 4; ntp++) {
                uint32_t bf[4];
                ldsm4(bf, bB + ntp * (16 * SB_ROW) + ks * 32);
                #pragma unroll
                for (int mt = 0; mt < 2; mt++) {
                    mma16816(acc[mt][ntp * 2 + 0], ah[mt], bf[0], bf[2]);
                    mma16816(acc[mt][ntp * 2 + 1], ah[mt], bf[1], bf[3]);
                }
            }
        }
        if (c < 7) __syncthreads();
    }

    // ---- epilogue: MUFU tanh + score reduce over this CTA's 128 cols ----
    const float* sbias = (const float*)(smem + SBIAS);
    const float* ssw   = (const float*)(smem + SSW);
    float* sred        = (float*)(smem + SRED);

    #pragma unroll
    for (int mt = 0; mt < 2; mt++) {
        #pragma unroll
        for (int h = 0; h < 2; h++) {
            float part = 0.0f;
            const int lrow_out = wr * 32 + mt * 16 + (lane >> 2) + h * 8;
            #pragma unroll
            for (int nt = 0; nt < 8; nt++) {
                const int col = wc * 64 + nt * 8 + (lane & 3) * 2;  // 0..127
                float2 bb = *reinterpret_cast<const float2*>(&sbias[col]);
                float2 ws = *reinterpret_cast<const float2*>(&ssw[col]);
                part = fmaf(tanh_mufu(acc[mt][nt][h * 2 + 0] + bb.x), ws.x, part);
                part = fmaf(tanh_mufu(acc[mt][nt][h * 2 + 1] + bb.y), ws.y, part);
            }
            part += __shfl_xor_sync(0xffffffffu, part, 1);
            part += __shfl_xor_sync(0xffffffffu, part, 2);
            if ((lane & 3) == 0) sred[wc * 128 + lrow_out] = part;
        }
    }
    __syncthreads();
    if (tid < 128)
        g_epart[(size_t)half * M_ROWS + row0 + tid] =
            sred[tid] + sred[128 + tid];
}

// ---------------------------------------------------------------------------
// Kernel B: causal softmax-weighted prefix average; sums the two N-halves
// of the score during the gather.
// ---------------------------------------------------------------------------
__global__ __launch_bounds__(256)
void attend_kernel(const float* __restrict__ H, float* __restrict__ C)
{
    __shared__ float se[TT];
    __shared__ float sw[TT];
    __shared__ float sinv[TT];

    const int n   = blockIdx.x;
    const int tid = threadIdx.x;

    for (int t = tid; t < TT; t += 256)
        se[t] = g_epart[t * NN + n] + g_epart[M_ROWS + t * NN + n];
    __syncthreads();

    if (tid == 0) {
        float m = -INFINITY;
        #pragma unroll 8
        for (int t = 0; t < TT; t++) m = fmaxf(m, se[t]);
        float s = 0.0f;
        for (int t = 0; t < TT; t++) {
            float w = __expf(se[t] - m);
            s += w;
            sw[t]   = w;
            sinv[t] = __fdividef(1.0f, s);
        }
    }
    __syncthreads();

    const size_t stride = (size_t)NN * DD;
    const float* hp = H + (size_t)n * DD + tid;
    float*       cp = C + (size_t)n * DD + tid;

    float num = 0.0f;
    #pragma unroll 8
    for (int t = 0; t < TT; t++) {
        float h = __ldcs(hp + (size_t)t * stride);
        num = fmaf(sw[t], h, num);
        __stcs(cp + (size_t)t * stride, num * sinv[t]);
    }
}

// ---------------------------------------------------------------------------
extern "C" void kernel_launch(void* const* d_in, const int* in_sizes, int n_in,
                              void* d_out, int out_size)
{
    const float* H  = (const float*)d_in[0];
    const float* W  = (const float*)d_in[1];
    const float* b  = (const float*)d_in[2];
    const float* sv = (const float*)d_in[3];
    float* C = (float*)d_out;

    cudaFuncSetAttribute(gemm_score_hmma,
                         cudaFuncAttributeMaxDynamicSharedMemorySize, SMTOT);

    w_prep<<<16, 512>>>(W);
    gemm_score_hmma<<<(M_ROWS / 128) * 2, 256, SMTOT>>>(H, b, sv);
    attend_kernel<<<NN, 256>>>(H, C);
}

// round 7
// speedup vs baseline: 1.3732x; 1.3732x over previous
#include <cuda_runtime.h>
#include <cuda_fp16.h>
#include <math.h>
#include <stdint.h>

#define TT 512
#define NN 1024
#define DD 256
#define M_ROWS (TT * NN)

__device__ float g_e[M_ROWS];
__device__ __align__(16) __half g_Whi[DD * DD];

// ---------------------------------------------------------------------------
// SMEM (per CTA, 54272 B -> 2 CTAs/SM). 80B rows (32 halves + 16B pad).
//   B double-buffer: 2 * 256 rows * 80
//   A double-buffer: 2 * 64 rows * 80
// ---------------------------------------------------------------------------
#define SB(buf)    ((buf) * 20480)
#define SA(buf)    (40960 + (buf) * 5120)
#define SBIAS      51200
#define SSW        52224
#define SRED       53248
#define SMTOT      54272

// ---------------------------------------------------------------------------
// PTX helpers (baseline ISA only -- toolchain targets sm_103, no tcgen05)
// ---------------------------------------------------------------------------
__device__ __forceinline__ uint32_t smem_u32(const void* p) {
    uint32_t a;
    asm("{ .reg .u64 t; cvta.to.shared.u64 t, %1; cvt.u32.u64 %0, t; }"
        : "=r"(a) : "l"(p));
    return a;
}
__device__ __forceinline__ void cp_async16(uint32_t dst, const void* src) {
    asm volatile("cp.async.cg.shared.global [%0], [%1], 16;"
                 :: "r"(dst), "l"(src) : "memory");
}
#define CP_COMMIT() asm volatile("cp.async.commit_group;" ::: "memory")
#define CP_WAIT(n)  asm volatile("cp.async.wait_group %0;" :: "n"(n) : "memory")

__device__ __forceinline__ void ldsm4(uint32_t* r, uint32_t addr) {
    asm volatile("ldmatrix.sync.aligned.m8n8.x4.shared.b16 {%0,%1,%2,%3}, [%4];"
                 : "=r"(r[0]), "=r"(r[1]), "=r"(r[2]), "=r"(r[3]) : "r"(addr));
}
__device__ __forceinline__ void mma16816(float* c, const uint32_t* a,
                                         uint32_t b0, uint32_t b1) {
    asm volatile(
        "mma.sync.aligned.m16n8k16.row.col.f32.f16.f16.f32 "
        "{%0,%1,%2,%3}, {%4,%5,%6,%7}, {%8,%9}, {%0,%1,%2,%3};"
        : "+f"(c[0]), "+f"(c[1]), "+f"(c[2]), "+f"(c[3])
        : "r"(a[0]), "r"(a[1]), "r"(a[2]), "r"(a[3]), "r"(b0), "r"(b1));
}

// fp32 x8 -> fp16 x8
__device__ __forceinline__ uint4 cvt8hi(const float4& u, const float4& v) {
    __half2 h0 = __floats2half2_rn(u.x, u.y);
    __half2 h1 = __floats2half2_rn(u.z, u.w);
    __half2 h2 = __floats2half2_rn(v.x, v.y);
    __half2 h3 = __floats2half2_rn(v.z, v.w);
    uint4 hi;
    hi.x = *(uint32_t*)&h0; hi.y = *(uint32_t*)&h1;
    hi.z = *(uint32_t*)&h2; hi.w = *(uint32_t*)&h3;
    return hi;
}

// tanh via MUFU (EX2 + RCP), rel err ~1e-6
__device__ __forceinline__ float tanh_mufu(float z) {
    float u = __expf(2.0f * z);
    return 1.0f - __fdividef(2.0f, u + 1.0f);
}

// ---------------------------------------------------------------------------
__global__ void w_prep(const float* __restrict__ W) {
    int i = blockIdx.x * blockDim.x + threadIdx.x;
    const float4* p = reinterpret_cast<const float4*>(W) + i * 2;
    reinterpret_cast<uint4*>(g_Whi)[i] = cvt8hi(p[0], p[1]);
}

// ---------------------------------------------------------------------------
// Kernel A: fp16 HMMA GEMM, BM=64 x BN=256, 256 threads, 2 CTAs/SM.
// grid = 8192 (M/64). 8 warps: 2 row-groups x 4 col-groups, warp tile 32x64.
// ---------------------------------------------------------------------------
__global__ __launch_bounds__(256, 2)
void gemm_score_hmma(const float* __restrict__ H,
                     const float* __restrict__ bias,
                     const float* __restrict__ swt)
{
    extern __shared__ char smem[];
    const uint32_t sb = smem_u32(smem);
    const int tid  = threadIdx.x;
    const int lane = tid & 31;
    const int warp = tid >> 5;          // 0..7
    const int wr   = warp >> 2;         // 0..1: rows 32*wr
    const int wc   = warp & 3;          // 0..3: cols 64*wc
    const int row0 = blockIdx.x * 64;

    if (tid < 256) {
        ((float*)(smem + SBIAS))[tid] = bias[tid];
        ((float*)(smem + SSW))[tid]   = swt[tid];
    }

    // A loader: 64 rows x 4 ksegs = 256 slots, one per thread
    const int arow  = tid >> 2;
    const int akseg = tid & 3;
    const float* aptr = H + (size_t)(row0 + arow) * DD + akseg * 8;
    const uint32_t a_sts = (uint32_t)(arow * 80 + akseg * 16);

    float acc[2][8][4];
    #pragma unroll
    for (int m = 0; m < 2; m++)
        #pragma unroll
        for (int n = 0; n < 8; n++)
            #pragma unroll
            for (int e = 0; e < 4; e++) acc[m][n][e] = 0.0f;

    // B cp.async: 1024 x 16B per chunk -> 4 per thread
    auto cpB = [&](int c, int buf) {
        #pragma unroll
        for (int p = 0; p < 4; p++) {
            int idx = tid + p * 256;
            int r   = idx >> 2;
            int ch  = idx & 3;
            cp_async16(sb + SB(buf) + r * 80 + ch * 16,
                       g_Whi + (size_t)r * DD + c * 32 + ch * 8);
        }
        CP_COMMIT();
    };

    // ldmatrix lane addressing
    const int lrow = lane & 15;
    const int lkh  = lane >> 4;
    const uint32_t aAddr = sb + 40960u +
                           (uint32_t)((wr * 32 + lrow) * 80 + lkh * 16);
    const uint32_t bAddr = sb + (uint32_t)((wc * 64 + lrow) * 80 + lkh * 16);

    // ---- prologue ----
    float4 ar0, ar1;
    cpB(0, 0);
    ar0 = *reinterpret_cast<const float4*>(aptr);
    ar1 = *reinterpret_cast<const float4*>(aptr + 4);
    *reinterpret_cast<uint4*>(smem + SA(0) + a_sts) = cvt8hi(ar0, ar1);
    ar0 = *reinterpret_cast<const float4*>(aptr + 32);
    ar1 = *reinterpret_cast<const float4*>(aptr + 36);
    CP_WAIT(0);
    __syncthreads();

    #pragma unroll
    for (int c = 0; c < 8; c++) {
        const int buf = c & 1;
        if (c < 7) {
            cpB(c + 1, buf ^ 1);
            *reinterpret_cast<uint4*>(smem + SA(buf ^ 1) + a_sts) =
                cvt8hi(ar0, ar1);
        }
        if (c < 6) {
            ar0 = *reinterpret_cast<const float4*>(aptr + (c + 2) * 32);
            ar1 = *reinterpret_cast<const float4*>(aptr + (c + 2) * 32 + 4);
        }

        // ---- MMA chunk c ----
        const uint32_t aA = aAddr + (uint32_t)(buf * 5120);
        const uint32_t bB = bAddr + (uint32_t)SB(buf);
        #pragma unroll
        for (int ks = 0; ks < 2; ks++) {
            uint32_t ah[2][4];
            ldsm4(ah[0], aA + ks * 32);
            ldsm4(ah[1], aA + 16 * 80 + ks * 32);
            #pragma unroll
            for (int ntp = 0; ntp < 4; ntp++) {
                uint32_t bf[4];
                ldsm4(bf, bB + ntp * (16 * 80) + ks * 32);
                #pragma unroll
                for (int mt = 0; mt < 2; mt++) {
                    mma16816(acc[mt][ntp * 2 + 0], ah[mt], bf[0], bf[2]);
                    mma16816(acc[mt][ntp * 2 + 1], ah[mt], bf[1], bf[3]);
                }
            }
        }
        if (c < 7) {
            CP_WAIT(0);
            __syncthreads();
        }
    }

    // ---- epilogue: MUFU tanh + score reduce over 256 e-columns ----
    const float* sbias = (const float*)(smem + SBIAS);
    const float* ssw   = (const float*)(smem + SSW);
    float* sred        = (float*)(smem + SRED);

    #pragma unroll
    for (int mt = 0; mt < 2; mt++) {
        #pragma unroll
        for (int h = 0; h < 2; h++) {
            float part = 0.0f;
            const int lrow_out = wr * 32 + mt * 16 + (lane >> 2) + h * 8;
            #pragma unroll
            for (int nt = 0; nt < 8; nt++) {
                const int col = wc * 64 + nt * 8 + (lane & 3) * 2;
                float2 bb = *reinterpret_cast<const float2*>(&sbias[col]);
                float2 ws = *reinterpret_cast<const float2*>(&ssw[col]);
                part = fmaf(tanh_mufu(acc[mt][nt][h * 2 + 0] + bb.x), ws.x, part);
                part = fmaf(tanh_mufu(acc[mt][nt][h * 2 + 1] + bb.y), ws.y, part);
            }
            part += __shfl_xor_sync(0xffffffffu, part, 1);
            part += __shfl_xor_sync(0xffffffffu, part, 2);
            if ((lane & 3) == 0) sred[wc * 64 + lrow_out] = part;
        }
    }
    __syncthreads();
    if (tid < 64)
        g_e[row0 + tid] = (sred[tid] + sred[64 + tid]) +
                          (sred[128 + tid] + sred[192 + tid]);
}

// ---------------------------------------------------------------------------
// Kernel B: causal softmax-weighted prefix average.
// ---------------------------------------------------------------------------
__global__ __launch_bounds__(256)
void attend_kernel(const float* __restrict__ H, float* __restrict__ C)
{
    __shared__ float se[TT];
    __shared__ float sw[TT];
    __shared__ float sinv[TT];

    const int n   = blockIdx.x;
    const int tid = threadIdx.x;

    for (int t = tid; t < TT; t += 256)
        se[t] = g_e[t * NN + n];
    __syncthreads();

    if (tid == 0) {
        float m = -INFINITY;
        #pragma unroll 8
        for (int t = 0; t < TT; t++) m = fmaxf(m, se[t]);
        float s = 0.0f;
        for (int t = 0; t < TT; t++) {
            float w = __expf(se[t] - m);
            s += w;
            sw[t]   = w;
            sinv[t] = __fdividef(1.0f, s);
        }
    }
    __syncthreads();

    const size_t stride = (size_t)NN * DD;
    const float* hp = H + (size_t)n * DD + tid;
    float*       cp = C + (size_t)n * DD + tid;

    float num = 0.0f;
    #pragma unroll 8
    for (int t = 0; t < TT; t++) {
        float h = __ldcs(hp + (size_t)t * stride);
        num = fmaf(sw[t], h, num);
        __stcs(cp + (size_t)t * stride, num * sinv[t]);
    }
}

// ---------------------------------------------------------------------------
extern "C" void kernel_launch(void* const* d_in, const int* in_sizes, int n_in,
                              void* d_out, int out_size)
{
    const float* H  = (const float*)d_in[0];
    const float* W  = (const float*)d_in[1];
    const float* b  = (const float*)d_in[2];
    const float* sv = (const float*)d_in[3];
    float* C = (float*)d_out;

    cudaFuncSetAttribute(gemm_score_hmma,
                         cudaFuncAttributeMaxDynamicSharedMemorySize, SMTOT);

    w_prep<<<16, 512>>>(W);
    gemm_score_hmma<<<M_ROWS / 64, 256, SMTOT>>>(H, b, sv);
    attend_kernel<<<NN, 256>>>(H, C);
}